// round 14
// baseline (speedup 1.0000x reference)
#include <cuda_runtime.h>
#include <cuda_bf16.h>

#define N_USERS       6040
#define NUM_INPUTS    9992          // 6040 + 3952
#define NUM_W4        2498          // NUM_INPUTS / 4 exactly
#define FACT_NUM      16
#define BATCH         4194304
#define NGROUPS       (BATCH / 4)   // 1048576 groups of 4 rows
#define RATING_THRESH 3

#define TPB     512
#define NWARP   (TPB / 32)
#define BLOCKS  592                 // 148 SMs * 4: one wave, 64 warps/SM
#define GPB     1772                // groups per block: 592*1772 >= NGROUPS

// Single-producer (block 0) publishes; reset at end of every launch so each
// graph replay executes identically.
__device__ int   g_flag = 0;
__device__ int   g_done = 0;
__device__ float d_K;
__device__ int   d_mode;            // 0=general, 1=all 1.0f, 2=all 0.0f

// ints [12g,12g+12): a=(u0,m0,r0,u1) b=(m1,r1,u2,m2) c=(r2,u3,m3,r3)
__device__ __forceinline__ float4 rec4(const int4& a, const int4& b, const int4& c) {
    float4 r;
    r.x = (a.z >= RATING_THRESH) ? 1.0f : 0.0f;
    r.y = (b.y >= RATING_THRESH) ? 1.0f : 0.0f;
    r.z = (c.x >= RATING_THRESH) ? 1.0f : 0.0f;
    r.w = (c.w >= RATING_THRESH) ? 1.0f : 0.0f;
    return r;
}

__device__ __forceinline__ float fast_sigmoid(float z) {
    if (z > 10.0f)  return 1.0f;
    if (z < -10.0f) return 0.0f;
    return 1.0f / (1.0f + __expf(-z));
}

__global__ __launch_bounds__(TPB, 4)   // cap regs at 32 -> 64 warps/SM
void fm_all(const int4* __restrict__ x4,
            const float* __restrict__ w,
            const float* __restrict__ emb,
            const float* __restrict__ bias,
            float* __restrict__ out) {
    // Union buffer: fast path stages r here (GPB float4 = 28KB <= 40KB);
    // general path reuses it for the w gather table.
    __shared__ float sbuf[NUM_INPUTS];
    __shared__ float s_red[NWARP];
    __shared__ float s_K;
    __shared__ int   s_mode;

    const int tid = threadIdx.x;
    const int g0  = blockIdx.x * GPB;                 // contiguous slice
    const int cnt = min(GPB, NGROUPS - g0);
    float4* __restrict__ sbuf4 = (float4*)sbuf;

    float4* __restrict__ o_out = (float4*)out;
    float4* __restrict__ r_out = (float4*)(out + BATCH);

    float K = 0.0f;
    int   mode = 0;

    if (blockIdx.x == 0) {
        // ---- Producer: scan w once for max|w|, compute K, publish ----
        const float4* __restrict__ w4 = (const float4*)w;
        float ma = 0.0f;
        #pragma unroll
        for (int i = tid; i < NUM_W4; i += TPB) {
            float4 v = w4[i];
            ma = fmaxf(ma, fmaxf(fmaxf(fabsf(v.x), fabsf(v.y)),
                                 fmaxf(fabsf(v.z), fabsf(v.w))));
        }
        #pragma unroll
        for (int s = 16; s > 0; s >>= 1)
            ma = fmaxf(ma, __shfl_xor_sync(0xffffffffu, ma, s));
        if ((tid & 31) == 0) s_red[tid >> 5] = ma;
        __syncthreads();
        if (tid == 0) {
            #pragma unroll
            for (int i = 1; i < NWARP; ++i) ma = fmaxf(ma, s_red[i]);
            ma = fmaxf(ma, s_red[0]);

            const float c0f = (float)(NUM_INPUTS - 2);
            const float c1f = 2.0f;
            float acc = 0.0f;
            #pragma unroll
            for (int k = 0; k < FACT_NUM; ++k) {
                float e0 = __ldg(emb + k);
                float e1 = __ldg(emb + FACT_NUM + k);
                float se = c0f * e0 + c1f * e1;
                float sq = c0f * e0 * e0 + c1f * e1 * e1;
                acc += se * se - sq;
            }
            float Kv = 0.5f * acc + __ldg(bias);
            // fp32 sigmoid rounds to exactly 1.0f for z>~17, 0.0f for z<-88.
            // Linear term bounded by +/- 2*max|w|; margins generous.
            int m = 0;
            if (Kv - 2.0f * ma > 20.0f)       m = 1;
            else if (Kv + 2.0f * ma < -25.0f) m = 2;
            d_K = Kv; d_mode = m;
            __threadfence();
            atomicExch(&g_flag, 1);          // release publish
            s_K = Kv; s_mode = m;
        }
        __syncthreads();
        K = s_K; mode = s_mode;
    }

    // ---- Phase A: PURE READ stream over this block's contiguous x slice;
    //      r staged to smem. Mode-independent, so all blocks start at t=0. ----
    for (int l = tid; l < cnt; l += TPB) {
        const int g = g0 + l;
        int4 a = x4[3 * g + 0];
        int4 b = x4[3 * g + 1];
        int4 c = x4[3 * g + 2];
        sbuf4[l] = rec4(a, b, c);
    }
    __syncthreads();

    // ---- Acquire (K, mode) for consumer blocks ----
    if (blockIdx.x != 0) {
        if (tid == 0) {
            while (atomicAdd(&g_flag, 0) == 0) { __nanosleep(128); }
            __threadfence();
            s_K = d_K; s_mode = d_mode;
        }
        __syncthreads();
        K = s_K; mode = s_mode;
    }

    if (mode != 0) {
        // ---- Phase B: PURE WRITE stream — staged r + constant o ----
        const float ov = (mode == 1) ? 1.0f : 0.0f;
        const float4 oc = make_float4(ov, ov, ov, ov);
        for (int l = tid; l < cnt; l += TPB) {
            const int g = g0 + l;
            r_out[g] = sbuf4[l];
            o_out[g] = oc;
        }
    } else {
        // ---- General fallback ----
        // 1) dump staged r (frees the union buffer)
        for (int l = tid; l < cnt; l += TPB)
            r_out[g0 + l] = sbuf4[l];
        __syncthreads();
        // 2) stage w gather table into the union buffer
        for (int i = tid; i < NUM_INPUTS; i += TPB)
            sbuf[i] = w[i];
        __syncthreads();
        // 3) recompute o from x (L2-warm) via smem gathers
        for (int l = tid; l < cnt; l += TPB) {
            const int g = g0 + l;
            int4 a = x4[3 * g + 0];
            int4 b = x4[3 * g + 1];
            int4 c = x4[3 * g + 2];
            float4 o;
            o.x = fast_sigmoid(sbuf[a.x] + sbuf[N_USERS + a.y] + K);
            o.y = fast_sigmoid(sbuf[a.w] + sbuf[N_USERS + b.x] + K);
            o.z = fast_sigmoid(sbuf[b.z] + sbuf[N_USERS + b.w] + K);
            o.w = fast_sigmoid(sbuf[c.y] + sbuf[N_USERS + c.z] + K);
            o_out[g] = o;
        }
    }

    // ---- Launch-end reset so every graph replay runs identically ----
    __syncthreads();
    if (tid == 0) {
        int v = atomicAdd(&g_done, 1);
        if (v == BLOCKS - 1) {
            g_done = 0;
            __threadfence();
            atomicExch(&g_flag, 0);
        }
    }
}

extern "C" void kernel_launch(void* const* d_in, const int* in_sizes, int n_in,
                              void* d_out, int out_size) {
    const int*   x   = (const int*)d_in[0];     // (BATCH, 3) int32
    const float* emb = (const float*)d_in[1];   // (9992, 16) f32
    const float* lw  = (const float*)d_in[2];   // (1, 9992) f32
    const float* lb  = (const float*)d_in[3];   // (1,) f32
    float*       out = (float*)d_out;           // [out(4M) | recommended(4M)]

    fm_all<<<BLOCKS, TPB>>>((const int4*)x, lw, emb, lb, out);
    (void)in_sizes; (void)n_in; (void)out_size;
}

// round 15
// speedup vs baseline: 1.1448x; 1.1448x over previous
#include <cuda_runtime.h>
#include <cuda_bf16.h>

#define N_USERS       6040
#define NUM_INPUTS    9992          // 6040 + 3952
#define NUM_W4        2498          // NUM_INPUTS / 4 exactly
#define FACT_NUM      16
#define BATCH         4194304
#define NGROUPS       (BATCH / 4)   // 1048576 groups of 4 rows
#define RATING_THRESH 3

#define TPB     512
#define NWARP   (TPB / 32)
#define BLOCKS  592                 // 148 SMs * 4 blocks: one balanced wave
#define GSTRIDE (BLOCKS * TPB)      // 303104

// ints [12g,12g+12): a=(u0,m0,r0,u1) b=(m1,r1,u2,m2) c=(r2,u3,m3,r3)
__device__ __forceinline__ float4 rec4(const int4& a, const int4& b, const int4& c) {
    float4 r;
    r.x = (a.z >= RATING_THRESH) ? 1.0f : 0.0f;
    r.y = (b.y >= RATING_THRESH) ? 1.0f : 0.0f;
    r.z = (c.x >= RATING_THRESH) ? 1.0f : 0.0f;
    r.w = (c.w >= RATING_THRESH) ? 1.0f : 0.0f;
    return r;
}

__device__ __forceinline__ float fast_sigmoid(float z) {
    // Saturation fast path avoids MUFU when |z| is large; the reference fp32
    // sigmoid rounds to exactly 1.0f above ~17 anyway.
    if (z > 10.0f)  return 1.0f;
    if (z < -10.0f) return 0.0f;
    return 1.0f / (1.0f + __expf(-z));
}

__global__ __launch_bounds__(TPB, 4)   // cap regs at 32 -> 64 warps/SM
void fm_all(const int4* __restrict__ x4,
            const float* __restrict__ w,
            const float* __restrict__ emb,
            const float* __restrict__ bias,
            float* __restrict__ out) {
    // Table only touched on the general path. 4 blocks x 40KB = 160KB <= 228KB,
    // so smem is not the occupancy cap; warps are (64/SM).
    __shared__ float sw[NUM_INPUTS];
    __shared__ float s_red[NWARP];
    __shared__ float s_K;
    __shared__ int   s_mode;

    const int tid  = threadIdx.x;
    const int base = blockIdx.x * TPB + tid;

    float4* __restrict__ o_out = (float4*)out;
    float4* __restrict__ r_out = (float4*)(out + BATCH);

    // ---- Preload iteration-0 x (overlaps the w scan below) ----
    int4 a = x4[3 * base + 0];
    int4 b = x4[3 * base + 1];
    int4 c = x4[3 * base + 2];

    // ---- Per-block saturation-mode scan: max|w| ----
    {
        const float4* __restrict__ w4 = (const float4*)w;
        float ma = 0.0f;
        for (int i = tid; i < NUM_W4; i += TPB) {
            float4 v = w4[i];
            ma = fmaxf(ma, fmaxf(fmaxf(fabsf(v.x), fabsf(v.y)),
                                 fmaxf(fabsf(v.z), fabsf(v.w))));
        }
        #pragma unroll
        for (int s = 16; s > 0; s >>= 1)
            ma = fmaxf(ma, __shfl_xor_sync(0xffffffffu, ma, s));
        if ((tid & 31) == 0) s_red[tid >> 5] = ma;
        __syncthreads();
        if (tid == 0) {
            #pragma unroll
            for (int i = 1; i < NWARP; ++i) ma = fmaxf(ma, s_red[i]);
            ma = fmaxf(ma, s_red[0]);

            const float c0f = (float)(NUM_INPUTS - 2);
            const float c1f = 2.0f;
            float acc = 0.0f;
            #pragma unroll
            for (int k = 0; k < FACT_NUM; ++k) {
                float e0 = __ldg(emb + k);
                float e1 = __ldg(emb + FACT_NUM + k);
                float se = c0f * e0 + c1f * e1;
                float sq = c0f * e0 * e0 + c1f * e1 * e1;
                acc += se * se - sq;
            }
            float K = 0.5f * acc + __ldg(bias);
            // fp32 sigmoid rounds to exactly 1.0f for z>~17, 0.0f for z<-88.
            // Linear term bounded by +/- 2*max|w|; margins generous.
            int mode = 0;
            if (K - 2.0f * ma > 20.0f)       mode = 1;
            else if (K + 2.0f * ma < -25.0f) mode = 2;
            s_K = K; s_mode = mode;
        }
        __syncthreads();
    }
    const float K   = s_K;
    const int  mode = s_mode;

    if (mode != 0) {
        // ---- Saturated fast path: constant out, predicate rec ----
        const float ov = (mode == 1) ? 1.0f : 0.0f;
        const float4 oc = make_float4(ov, ov, ov, ov);

        int g = base;
        while (true) {
            o_out[g] = oc;                 // no load dependence
            r_out[g] = rec4(a, b, c);
            g += GSTRIDE;
            if (g >= NGROUPS) break;
            a = x4[3 * g + 0];
            b = x4[3 * g + 1];
            c = x4[3 * g + 2];
        }
        return;
    }

    // ---- General fallback: smem-staged table gathers ----
    for (int i = tid; i < NUM_INPUTS; i += TPB)
        sw[i] = w[i];
    __syncthreads();

    int g = base;
    while (true) {
        float4 o;
        o.x = fast_sigmoid(sw[a.x] + sw[N_USERS + a.y] + K);
        o.y = fast_sigmoid(sw[a.w] + sw[N_USERS + b.x] + K);
        o.z = fast_sigmoid(sw[b.z] + sw[N_USERS + b.w] + K);
        o.w = fast_sigmoid(sw[c.y] + sw[N_USERS + c.z] + K);
        o_out[g] = o;
        r_out[g] = rec4(a, b, c);
        g += GSTRIDE;
        if (g >= NGROUPS) break;
        a = x4[3 * g + 0];
        b = x4[3 * g + 1];
        c = x4[3 * g + 2];
    }
}

extern "C" void kernel_launch(void* const* d_in, const int* in_sizes, int n_in,
                              void* d_out, int out_size) {
    const int*   x   = (const int*)d_in[0];     // (BATCH, 3) int32
    const float* emb = (const float*)d_in[1];   // (9992, 16) f32
    const float* lw  = (const float*)d_in[2];   // (1, 9992) f32
    const float* lb  = (const float*)d_in[3];   // (1,) f32
    float*       out = (float*)d_out;           // [out(4M) | recommended(4M)]

    fm_all<<<BLOCKS, TPB>>>((const int4*)x, lw, emb, lb, out);
    (void)in_sizes; (void)n_in; (void)out_size;
}

// round 16
// speedup vs baseline: 1.1473x; 1.0022x over previous
#include <cuda_runtime.h>
#include <cuda_bf16.h>

#define N_USERS       6040
#define NUM_INPUTS    9992          // 6040 + 3952
#define NUM_W4        2498          // NUM_INPUTS / 4 exactly
#define FACT_NUM      16
#define BATCH         4194304
#define NGROUPS       (BATCH / 4)   // 1048576 groups of 4 rows
#define RATING_THRESH 3

#define TPB     512
#define NWARP   (TPB / 32)
#define BLOCKS  592                 // 148 SMs * 4 blocks: one balanced wave
#define GSTRIDE (BLOCKS * TPB)      // 303104

// ints [12g,12g+12): a=(u0,m0,r0,u1) b=(m1,r1,u2,m2) c=(r2,u3,m3,r3)
__device__ __forceinline__ float4 rec4(const int4& a, const int4& b, const int4& c) {
    float4 r;
    r.x = (a.z >= RATING_THRESH) ? 1.0f : 0.0f;
    r.y = (b.y >= RATING_THRESH) ? 1.0f : 0.0f;
    r.z = (c.x >= RATING_THRESH) ? 1.0f : 0.0f;
    r.w = (c.w >= RATING_THRESH) ? 1.0f : 0.0f;
    return r;
}

__device__ __forceinline__ float fast_sigmoid(float z) {
    // Saturation fast path avoids MUFU when |z| is large; the reference fp32
    // sigmoid rounds to exactly 1.0f above ~17 anyway.
    if (z > 10.0f)  return 1.0f;
    if (z < -10.0f) return 0.0f;
    return 1.0f / (1.0f + __expf(-z));
}

__global__ __launch_bounds__(TPB, 4)   // cap regs at 32 -> 64 warps/SM
void fm_all(const int4* __restrict__ x4,
            const float* __restrict__ w,
            const float* __restrict__ emb,
            const float* __restrict__ bias,
            float* __restrict__ out) {
    // Table only touched on the general path. 4 blocks x 40KB = 160KB <= 228KB,
    // so smem is not the occupancy cap; warps are (64/SM).
    __shared__ float sw[NUM_INPUTS];
    __shared__ float s_red[NWARP];
    __shared__ float s_K;
    __shared__ int   s_mode;

    const int tid  = threadIdx.x;
    const int base = blockIdx.x * TPB + tid;

    float4* __restrict__ o_out = (float4*)out;
    float4* __restrict__ r_out = (float4*)(out + BATCH);

    // ---- Preload iteration-0 x (overlaps the w scan below) ----
    int4 a = x4[3 * base + 0];
    int4 b = x4[3 * base + 1];
    int4 c = x4[3 * base + 2];

    // ---- Per-block saturation-mode scan: max|w| ----
    {
        const float4* __restrict__ w4 = (const float4*)w;
        float ma = 0.0f;
        for (int i = tid; i < NUM_W4; i += TPB) {
            float4 v = w4[i];
            ma = fmaxf(ma, fmaxf(fmaxf(fabsf(v.x), fabsf(v.y)),
                                 fmaxf(fabsf(v.z), fabsf(v.w))));
        }
        #pragma unroll
        for (int s = 16; s > 0; s >>= 1)
            ma = fmaxf(ma, __shfl_xor_sync(0xffffffffu, ma, s));
        if ((tid & 31) == 0) s_red[tid >> 5] = ma;
        __syncthreads();
        if (tid == 0) {
            #pragma unroll
            for (int i = 1; i < NWARP; ++i) ma = fmaxf(ma, s_red[i]);
            ma = fmaxf(ma, s_red[0]);

            const float c0f = (float)(NUM_INPUTS - 2);
            const float c1f = 2.0f;
            float acc = 0.0f;
            #pragma unroll
            for (int k = 0; k < FACT_NUM; ++k) {
                float e0 = __ldg(emb + k);
                float e1 = __ldg(emb + FACT_NUM + k);
                float se = c0f * e0 + c1f * e1;
                float sq = c0f * e0 * e0 + c1f * e1 * e1;
                acc += se * se - sq;
            }
            float K = 0.5f * acc + __ldg(bias);
            // fp32 sigmoid rounds to exactly 1.0f for z>~17, 0.0f for z<-88.
            // Linear term bounded by +/- 2*max|w|; margins generous.
            int mode = 0;
            if (K - 2.0f * ma > 20.0f)       mode = 1;
            else if (K + 2.0f * ma < -25.0f) mode = 2;
            s_K = K; s_mode = mode;
        }
        __syncthreads();
    }
    const float K   = s_K;
    const int  mode = s_mode;

    if (mode != 0) {
        // ---- Saturated fast path: constant out, predicate rec ----
        const float ov = (mode == 1) ? 1.0f : 0.0f;
        const float4 oc = make_float4(ov, ov, ov, ov);

        int g = base;
        while (true) {
            o_out[g] = oc;                 // no load dependence
            r_out[g] = rec4(a, b, c);
            g += GSTRIDE;
            if (g >= NGROUPS) break;
            a = x4[3 * g + 0];
            b = x4[3 * g + 1];
            c = x4[3 * g + 2];
        }
        return;
    }

    // ---- General fallback: smem-staged table gathers ----
    for (int i = tid; i < NUM_INPUTS; i += TPB)
        sw[i] = w[i];
    __syncthreads();

    int g = base;
    while (true) {
        float4 o;
        o.x = fast_sigmoid(sw[a.x] + sw[N_USERS + a.y] + K);
        o.y = fast_sigmoid(sw[a.w] + sw[N_USERS + b.x] + K);
        o.z = fast_sigmoid(sw[b.z] + sw[N_USERS + b.w] + K);
        o.w = fast_sigmoid(sw[c.y] + sw[N_USERS + c.z] + K);
        o_out[g] = o;
        r_out[g] = rec4(a, b, c);
        g += GSTRIDE;
        if (g >= NGROUPS) break;
        a = x4[3 * g + 0];
        b = x4[3 * g + 1];
        c = x4[3 * g + 2];
    }
}

extern "C" void kernel_launch(void* const* d_in, const int* in_sizes, int n_in,
                              void* d_out, int out_size) {
    const int*   x   = (const int*)d_in[0];     // (BATCH, 3) int32
    const float* emb = (const float*)d_in[1];   // (9992, 16) f32
    const float* lw  = (const float*)d_in[2];   // (1, 9992) f32
    const float* lb  = (const float*)d_in[3];   // (1,) f32
    float*       out = (float*)d_out;           // [out(4M) | recommended(4M)]

    fm_all<<<BLOCKS, TPB>>>((const int4*)x, lw, emb, lb, out);
    (void)in_sizes; (void)n_in; (void)out_size;
}